// round 7
// baseline (speedup 1.0000x reference)
#include <cuda_runtime.h>
#include <cstdint>

#define NN 100000
#define EE 3200000
#define H 128

// ---------------- scratch (__device__ globals; allocation-free rule) ----------------
__device__ float g_X[(size_t)NN * H];   // 51.2 MB ping
__device__ float g_A[(size_t)NN * H];   // 51.2 MB pong
__device__ float g_dinv[NN];
__device__ int   g_deg[100352];         // padded for int4 zeroing
__device__ int   g_off[NN + 1];
__device__ int   g_cur[100352];
__device__ int   g_csrc[EE];            // CSR: src per incoming edge of dst
__device__ float g_cnrm[EE];            // CSR: norm per incoming edge
__device__ int   g_is64;

__device__ __forceinline__ float fast_tanh(float x) {
    float t = __expf(-2.0f * fabsf(x));
    float r = __fdividef(1.0f - t, 1.0f + t);
    return copysignf(r, x);
}

// ---------------- edge dtype detection (int32 vs int64) ----------------
__global__ void detect_k(const int* __restrict__ ei32) {
    __shared__ int nz;
    if (threadIdx.x == 0) nz = 0;
    __syncthreads();
    int c = 0;
    for (int k = threadIdx.x; k < 4096; k += blockDim.x)
        if (ei32[2 * k + 1] != 0) c++;
    atomicAdd(&nz, c);
    __syncthreads();
    if (threadIdx.x == 0) g_is64 = (nz == 0) ? 1 : 0;
}

__device__ __forceinline__ int edge_val(const void* ei, long long E, long long idx, int row) {
    if (g_is64) return (int)((const long long*)ei)[row ? E + idx : idx];
    return ((const int*)ei)[row ? E + idx : idx];
}

// ---------------- zero ints ----------------
__global__ void zeroi_k(int4* __restrict__ p, int n4) {
    int i = blockIdx.x * blockDim.x + threadIdx.x;
    if (i < n4) p[i] = make_int4(0, 0, 0, 0);
}

// ---------------- degree count ----------------
__global__ void deg_k(const void* __restrict__ ei, long long E, int* __restrict__ deg) {
    long long e = (long long)blockIdx.x * blockDim.x + threadIdx.x;
    if (e < E) atomicAdd(&deg[edge_val(ei, E, e, 1)], 1);
}

__global__ void dinv_k(const int* __restrict__ deg, float* __restrict__ dinv, int n) {
    int i = blockIdx.x * blockDim.x + threadIdx.x;
    if (i < n) dinv[i] = rsqrtf((float)deg[i] + 2.0f);   // improved self-loop: +2
}

// ---------------- single-block scan: deg -> off, cur ----------------
__global__ void __launch_bounds__(1024) scan_k(const int* __restrict__ deg,
                                               int* __restrict__ off,
                                               int* __restrict__ cur, int n) {
    __shared__ int part[1024];
    int t = threadIdx.x;
    int chunk = (n + 1023) / 1024;
    int lo = t * chunk, hi = lo + chunk < n ? lo + chunk : n;
    int s = 0;
    for (int i = lo; i < hi; i++) s += deg[i];
    part[t] = s;
    __syncthreads();
    for (int o = 1; o < 1024; o <<= 1) {
        int v = (t >= o) ? part[t - o] : 0;
        __syncthreads();
        part[t] += v;
        __syncthreads();
    }
    int base = (t == 0) ? 0 : part[t - 1];
    for (int i = lo; i < hi; i++) {
        off[i] = base; cur[i] = base; base += deg[i];
    }
    if (t == 0) off[n] = part[1023];
}

// ---------------- CSR fill ----------------
__global__ void fill_k(const void* __restrict__ ei, long long E,
                       const float* __restrict__ dinv,
                       int* __restrict__ cur, int* __restrict__ csrc,
                       float* __restrict__ cnrm) {
    long long e = (long long)blockIdx.x * blockDim.x + threadIdx.x;
    if (e >= E) return;
    int s = edge_val(ei, E, e, 0);
    int d = edge_val(ei, E, e, 1);
    int pos = atomicAdd(&cur[d], 1);
    csrc[pos] = s;
    cnrm[pos] = dinv[s] * dinv[d];
}

// ---------------- gather + conv epilogue: out = tanh(sum + xw*2dinv^2 + b) ----------------
// 2-wide unroll (r3 form — 4-wide regressed ~50us via L1tex queue contention)
__global__ void __launch_bounds__(256) aggregate_k(
    const float* __restrict__ xw, const int* __restrict__ off,
    const int* __restrict__ deg, const int* __restrict__ csrc,
    const float* __restrict__ cnrm, const float* __restrict__ dinv,
    const float* __restrict__ bias, float* __restrict__ out, int n)
{
    int node = (blockIdx.x * 256 + threadIdx.x) >> 5;
    int lane = threadIdx.x & 31;
    if (node >= n) return;
    int j = off[node];
    int end = j + deg[node];
    const float4* X4 = (const float4*)xw;
    float4 acc = make_float4(0.f, 0.f, 0.f, 0.f);
    for (; j + 1 < end; j += 2) {
        int s0 = __ldg(&csrc[j]);     int s1 = __ldg(&csrc[j + 1]);
        float n0 = __ldg(&cnrm[j]);   float n1 = __ldg(&cnrm[j + 1]);
        float4 v0 = X4[(size_t)s0 * 32 + lane];
        float4 v1 = X4[(size_t)s1 * 32 + lane];
        acc.x = fmaf(v0.x, n0, acc.x); acc.y = fmaf(v0.y, n0, acc.y);
        acc.z = fmaf(v0.z, n0, acc.z); acc.w = fmaf(v0.w, n0, acc.w);
        acc.x = fmaf(v1.x, n1, acc.x); acc.y = fmaf(v1.y, n1, acc.y);
        acc.z = fmaf(v1.z, n1, acc.z); acc.w = fmaf(v1.w, n1, acc.w);
    }
    if (j < end) {
        int s0 = __ldg(&csrc[j]);
        float n0 = __ldg(&cnrm[j]);
        float4 v0 = X4[(size_t)s0 * 32 + lane];
        acc.x = fmaf(v0.x, n0, acc.x); acc.y = fmaf(v0.y, n0, acc.y);
        acc.z = fmaf(v0.z, n0, acc.z); acc.w = fmaf(v0.w, n0, acc.w);
    }
    float di = dinv[node];
    float sw = 2.0f * di * di;
    float4 xv = X4[(size_t)node * 32 + lane];
    float4 bv = ((const float4*)bias)[lane];
    acc.x = fast_tanh(fmaf(xv.x, sw, acc.x) + bv.x);
    acc.y = fast_tanh(fmaf(xv.y, sw, acc.y) + bv.y);
    acc.z = fast_tanh(fmaf(xv.z, sw, acc.z) + bv.z);
    acc.w = fast_tanh(fmaf(xv.w, sw, acc.w) + bv.w);
    ((float4*)out)[(size_t)node * 32 + lane] = acc;
}

// ---------------- GEMM [n,128] @ [128,128] (r3 form: 8 warps x 4 rows) ----------------
template <bool TANH, bool BIAS>
__global__ void __launch_bounds__(256) gemm128(
    const float* __restrict__ in, const float* __restrict__ W,
    const float* __restrict__ bias, float* __restrict__ out, int n)
{
    extern __shared__ float sm[];
    float4* Wsm4 = (float4*)sm;                  // 128x128 floats
    float*  Hsm  = sm + 16384;                   // 8 warps * 4 rows * 128
    float*  bsm  = sm + 16384 + 4096;

    int tid = threadIdx.x, lane = tid & 31, w = tid >> 5;

    const float4* W4 = (const float4*)W;
    #pragma unroll
    for (int i = tid; i < 4096; i += 256) Wsm4[i] = W4[i];
    if (tid < 128) bsm[tid] = BIAS ? bias[tid] : 0.0f;
    __syncthreads();

    int nb = (blockIdx.x * 8 + w) * 4;
    if (nb >= n) return;

    float4* H4 = (float4*)(Hsm + w * 512);
    #pragma unroll
    for (int j = 0; j < 4; j++) {
        int node = nb + j < n ? nb + j : n - 1;
        H4[j * 32 + lane] = ((const float4*)in)[(size_t)node * 32 + lane];
    }
    __syncwarp();

    float4 bv = ((float4*)bsm)[lane];
    float4 a0 = bv, a1 = bv, a2 = bv, a3 = bv;
    const float* Hw = Hsm + w * 512;

    #pragma unroll 8
    for (int k = 0; k < 128; k++) {
        float4 wv = Wsm4[k * 32 + lane];
        float h0 = Hw[k], h1 = Hw[128 + k], h2 = Hw[256 + k], h3 = Hw[384 + k];
        a0.x = fmaf(wv.x, h0, a0.x); a0.y = fmaf(wv.y, h0, a0.y);
        a0.z = fmaf(wv.z, h0, a0.z); a0.w = fmaf(wv.w, h0, a0.w);
        a1.x = fmaf(wv.x, h1, a1.x); a1.y = fmaf(wv.y, h1, a1.y);
        a1.z = fmaf(wv.z, h1, a1.z); a1.w = fmaf(wv.w, h1, a1.w);
        a2.x = fmaf(wv.x, h2, a2.x); a2.y = fmaf(wv.y, h2, a2.y);
        a2.z = fmaf(wv.z, h2, a2.z); a2.w = fmaf(wv.w, h2, a2.w);
        a3.x = fmaf(wv.x, h3, a3.x); a3.y = fmaf(wv.y, h3, a3.y);
        a3.z = fmaf(wv.z, h3, a3.z); a3.w = fmaf(wv.w, h3, a3.w);
    }

    float4 r[4] = {a0, a1, a2, a3};
    #pragma unroll
    for (int j = 0; j < 4; j++) {
        int node = nb + j;
        if (node >= n) break;
        float4 v = r[j];
        if (TANH) {
            v.x = fast_tanh(v.x); v.y = fast_tanh(v.y);
            v.z = fast_tanh(v.z); v.w = fast_tanh(v.w);
        }
        ((float4*)out)[(size_t)node * 32 + lane] = v;
    }
}

// ---------------- final 128 -> 3 ----------------
__global__ void __launch_bounds__(256) out_k(
    const float* __restrict__ h, const float* __restrict__ lw4,
    const float* __restrict__ lb4, float* __restrict__ out, int n)
{
    int wid = (blockIdx.x * 256 + threadIdx.x) >> 5;
    int lane = threadIdx.x & 31;
    if (wid >= n) return;
    const float* row = h + (size_t)wid * 128;
    float a0 = 0.f, a1 = 0.f, a2 = 0.f;
    #pragma unroll
    for (int k = lane; k < 128; k += 32) {
        float hv = row[k];
        a0 = fmaf(hv, __ldg(&lw4[k * 3 + 0]), a0);
        a1 = fmaf(hv, __ldg(&lw4[k * 3 + 1]), a1);
        a2 = fmaf(hv, __ldg(&lw4[k * 3 + 2]), a2);
    }
    #pragma unroll
    for (int o = 16; o; o >>= 1) {
        a0 += __shfl_down_sync(0xffffffffu, a0, o);
        a1 += __shfl_down_sync(0xffffffffu, a1, o);
        a2 += __shfl_down_sync(0xffffffffu, a2, o);
    }
    if (lane == 0) {
        out[(size_t)wid * 3 + 0] = a0 + lb4[0];
        out[(size_t)wid * 3 + 1] = a1 + lb4[1];
        out[(size_t)wid * 3 + 2] = a2 + lb4[2];
    }
}

// ---------------- launch ----------------
extern "C" void kernel_launch(void* const* d_in, const int* in_sizes, int n_in,
                              void* d_out, int out_size)
{
    const float* x   = (const float*)d_in[0];
    const void*  ei  = d_in[1];
    const float* W1  = (const float*)d_in[2];
    const float* b1  = (const float*)d_in[3];
    const float* W2  = (const float*)d_in[4];
    const float* b2  = (const float*)d_in[5];
    const float* lw1 = (const float*)d_in[6];
    const float* lb1 = (const float*)d_in[7];
    const float* lw2 = (const float*)d_in[8];
    const float* lb2 = (const float*)d_in[9];
    const float* lw3 = (const float*)d_in[10];
    const float* lb3 = (const float*)d_in[11];
    const float* lw4 = (const float*)d_in[12];
    const float* lb4 = (const float*)d_in[13];
    float* out = (float*)d_out;

    int n = in_sizes[0] / H;
    long long E = (long long)in_sizes[1] / 2;

    float *pX, *pA, *pD, *pNrm;
    int *pDeg, *pOff, *pCur, *pSrc;
    cudaGetSymbolAddress((void**)&pX, g_X);
    cudaGetSymbolAddress((void**)&pA, g_A);
    cudaGetSymbolAddress((void**)&pD, g_dinv);
    cudaGetSymbolAddress((void**)&pDeg, g_deg);
    cudaGetSymbolAddress((void**)&pOff, g_off);
    cudaGetSymbolAddress((void**)&pCur, g_cur);
    cudaGetSymbolAddress((void**)&pSrc, g_csrc);
    cudaGetSymbolAddress((void**)&pNrm, g_cnrm);

    const int smem = (16384 + 4096 + 128) * 4;   // 82432 B
    cudaFuncSetAttribute(gemm128<false, false>, cudaFuncAttributeMaxDynamicSharedMemorySize, smem);
    cudaFuncSetAttribute(gemm128<true,  true>,  cudaFuncAttributeMaxDynamicSharedMemorySize, smem);

    int gb  = (n + 31) / 32;               // gemm blocks
    int nwb = (n + 7) / 8;                 // warp-per-node blocks
    int eb  = (int)((E + 255) / 256);      // thread-per-edge blocks

    // Launch order puts gemm1 at my index 3 so ncu (-s 5 -c 1, with 2 harness
    // launches ahead of ours) captures the GEMM instead of dinv_k.
    detect_k<<<1, 256>>>((const int*)ei);                                  // 0
    zeroi_k<<<(100352 / 4 + 255) / 256, 256>>>((int4*)pDeg, 100352 / 4);   // 1
    deg_k<<<eb, 256>>>(ei, E, pDeg);                                       // 2
    gemm128<false, false><<<gb, 256, smem>>>(x, W1, nullptr, pX, n);       // 3 <- profiled
    dinv_k<<<(n + 255) / 256, 256>>>(pDeg, pD, n);                         // 4
    scan_k<<<1, 1024>>>(pDeg, pOff, pCur, n);                              // 5
    fill_k<<<eb, 256>>>(ei, E, pD, pCur, pSrc, pNrm);                      // 6

    // conv1 aggregate: A = tanh(gather(X) + self + b1)
    aggregate_k<<<nwb, 256>>>(pX, pOff, pDeg, pSrc, pNrm, pD, b1, pA, n);

    // conv2
    gemm128<false, false><<<gb, 256, smem>>>(pA, W2, nullptr, pX, n);
    aggregate_k<<<nwb, 256>>>(pX, pOff, pDeg, pSrc, pNrm, pD, b2, pA, n);

    // MLP head
    gemm128<true, true><<<gb, 256, smem>>>(pA, lw1, lb1, pX, n);
    gemm128<true, true><<<gb, 256, smem>>>(pX, lw2, lb2, pA, n);
    gemm128<true, true><<<gb, 256, smem>>>(pA, lw3, lb3, pX, n);
    out_k<<<(n + 7) / 8, 256>>>(pX, lw4, lb4, out, n);
}

// round 8
// speedup vs baseline: 1.7554x; 1.7554x over previous
#include <cuda_runtime.h>
#include <cstdint>

#define NN 100000
#define EE 3200000
#define H 128

// ---------------- scratch (__device__ globals; allocation-free rule) ----------------
__device__ float g_X[(size_t)NN * H];   // 51.2 MB ping
__device__ float g_A[(size_t)NN * H];   // 51.2 MB pong
__device__ float g_dinv[NN];
__device__ int   g_deg[100352];         // padded for int4 zeroing
__device__ int   g_off[NN + 1];
__device__ int   g_cur[100352];
__device__ int   g_csrc[EE];            // CSR: src per incoming edge of dst
__device__ float g_cnrm[EE];            // CSR: norm per incoming edge
__device__ int   g_is64;

__device__ __forceinline__ float fast_tanh(float x) {
    float t = __expf(-2.0f * fabsf(x));
    float r = __fdividef(1.0f - t, 1.0f + t);
    return copysignf(r, x);
}

// ---------------- edge dtype detection (int32 vs int64) ----------------
__global__ void detect_k(const int* __restrict__ ei32) {
    __shared__ int nz;
    if (threadIdx.x == 0) nz = 0;
    __syncthreads();
    int c = 0;
    for (int k = threadIdx.x; k < 4096; k += blockDim.x)
        if (ei32[2 * k + 1] != 0) c++;
    atomicAdd(&nz, c);
    __syncthreads();
    if (threadIdx.x == 0) g_is64 = (nz == 0) ? 1 : 0;
}

__device__ __forceinline__ int edge_val(const void* ei, long long E, long long idx, int row) {
    if (g_is64) return (int)((const long long*)ei)[row ? E + idx : idx];
    return ((const int*)ei)[row ? E + idx : idx];
}

// ---------------- zero ints ----------------
__global__ void zeroi_k(int4* __restrict__ p, int n4) {
    int i = blockIdx.x * blockDim.x + threadIdx.x;
    if (i < n4) p[i] = make_int4(0, 0, 0, 0);
}

// ---------------- degree count ----------------
__global__ void deg_k(const void* __restrict__ ei, long long E, int* __restrict__ deg) {
    long long e = (long long)blockIdx.x * blockDim.x + threadIdx.x;
    if (e < E) atomicAdd(&deg[edge_val(ei, E, e, 1)], 1);
}

__global__ void dinv_k(const int* __restrict__ deg, float* __restrict__ dinv, int n) {
    int i = blockIdx.x * blockDim.x + threadIdx.x;
    if (i < n) dinv[i] = rsqrtf((float)deg[i] + 2.0f);   // improved self-loop: +2
}

// ---------------- single-block scan: deg -> off, cur ----------------
__global__ void __launch_bounds__(1024) scan_k(const int* __restrict__ deg,
                                               int* __restrict__ off,
                                               int* __restrict__ cur, int n) {
    __shared__ int part[1024];
    int t = threadIdx.x;
    int chunk = (n + 1023) / 1024;
    int lo = t * chunk, hi = lo + chunk < n ? lo + chunk : n;
    int s = 0;
    for (int i = lo; i < hi; i++) s += deg[i];
    part[t] = s;
    __syncthreads();
    for (int o = 1; o < 1024; o <<= 1) {
        int v = (t >= o) ? part[t - o] : 0;
        __syncthreads();
        part[t] += v;
        __syncthreads();
    }
    int base = (t == 0) ? 0 : part[t - 1];
    for (int i = lo; i < hi; i++) {
        off[i] = base; cur[i] = base; base += deg[i];
    }
    if (t == 0) off[n] = part[1023];
}

// ---------------- CSR fill ----------------
__global__ void fill_k(const void* __restrict__ ei, long long E,
                       const float* __restrict__ dinv,
                       int* __restrict__ cur, int* __restrict__ csrc,
                       float* __restrict__ cnrm) {
    long long e = (long long)blockIdx.x * blockDim.x + threadIdx.x;
    if (e >= E) return;
    int s = edge_val(ei, E, e, 0);
    int d = edge_val(ei, E, e, 1);
    int pos = atomicAdd(&cur[d], 1);
    csrc[pos] = s;
    cnrm[pos] = dinv[s] * dinv[d];
}

// ---------------- gather + conv epilogue: out = tanh(sum + xw*2dinv^2 + b) ----------------
__global__ void __launch_bounds__(256) aggregate_k(
    const float* __restrict__ xw, const int* __restrict__ off,
    const int* __restrict__ deg, const int* __restrict__ csrc,
    const float* __restrict__ cnrm, const float* __restrict__ dinv,
    const float* __restrict__ bias, float* __restrict__ out, int n)
{
    int node = (blockIdx.x * 256 + threadIdx.x) >> 5;
    int lane = threadIdx.x & 31;
    if (node >= n) return;
    int j = off[node];
    int end = j + deg[node];
    const float4* X4 = (const float4*)xw;
    float4 acc = make_float4(0.f, 0.f, 0.f, 0.f);
    for (; j + 1 < end; j += 2) {
        int s0 = __ldg(&csrc[j]);     int s1 = __ldg(&csrc[j + 1]);
        float n0 = __ldg(&cnrm[j]);   float n1 = __ldg(&cnrm[j + 1]);
        float4 v0 = X4[(size_t)s0 * 32 + lane];
        float4 v1 = X4[(size_t)s1 * 32 + lane];
        acc.x = fmaf(v0.x, n0, acc.x); acc.y = fmaf(v0.y, n0, acc.y);
        acc.z = fmaf(v0.z, n0, acc.z); acc.w = fmaf(v0.w, n0, acc.w);
        acc.x = fmaf(v1.x, n1, acc.x); acc.y = fmaf(v1.y, n1, acc.y);
        acc.z = fmaf(v1.z, n1, acc.z); acc.w = fmaf(v1.w, n1, acc.w);
    }
    if (j < end) {
        int s0 = __ldg(&csrc[j]);
        float n0 = __ldg(&cnrm[j]);
        float4 v0 = X4[(size_t)s0 * 32 + lane];
        acc.x = fmaf(v0.x, n0, acc.x); acc.y = fmaf(v0.y, n0, acc.y);
        acc.z = fmaf(v0.z, n0, acc.z); acc.w = fmaf(v0.w, n0, acc.w);
    }
    float di = dinv[node];
    float sw = 2.0f * di * di;
    float4 xv = X4[(size_t)node * 32 + lane];
    float4 bv = ((const float4*)bias)[lane];
    acc.x = fast_tanh(fmaf(xv.x, sw, acc.x) + bv.x);
    acc.y = fast_tanh(fmaf(xv.y, sw, acc.y) + bv.y);
    acc.z = fast_tanh(fmaf(xv.z, sw, acc.z) + bv.z);
    acc.w = fast_tanh(fmaf(xv.w, sw, acc.w) + bv.w);
    ((float4*)out)[(size_t)node * 32 + lane] = acc;
}

// ---------------- GEMM via tf32 mma.sync (tensor cores) ----------------
// CTA tile 128 rows x 128 cols, K=128. 8 warps: warp = 32 rows x 64 cols.
// A staged [128][128] stride 132 (conflict-free); W staged transposed [c][k]
// stride 132 (conflict-free B frags). tf32 conversion (cvt.rna) at staging.
#define ASTRIDE 132
#define TC_SMEM (2 * 128 * ASTRIDE * 4)   // 135168 B

__device__ __forceinline__ float to_tf32(float x) {
    uint32_t u;
    asm("cvt.rna.tf32.f32 %0, %1;" : "=r"(u) : "f"(x));
    return __uint_as_float(u);
}

__device__ __forceinline__ void mma_tf32(float* c, const uint32_t* a,
                                         uint32_t b0, uint32_t b1) {
    asm volatile(
        "mma.sync.aligned.m16n8k8.row.col.f32.tf32.tf32.f32 "
        "{%0,%1,%2,%3}, {%4,%5,%6,%7}, {%8,%9}, {%0,%1,%2,%3};"
        : "+f"(c[0]), "+f"(c[1]), "+f"(c[2]), "+f"(c[3])
        : "r"(a[0]), "r"(a[1]), "r"(a[2]), "r"(a[3]), "r"(b0), "r"(b1));
}

template <bool TANH, bool BIAS>
__global__ void __launch_bounds__(256) gemm_tc(
    const float* __restrict__ in, const float* __restrict__ W,
    const float* __restrict__ bias, float* __restrict__ out, int n)
{
    extern __shared__ float sm[];
    float* Asm = sm;                        // [row][k] stride 132
    float* Wt  = sm + 128 * ASTRIDE;        // [c][k]  stride 132

    int tid = threadIdx.x, lane = tid & 31, w = tid >> 5;
    int nb = blockIdx.x * 128;

    // stage A (tf32-rounded), float4 per thread-iter
    const float4* In4 = (const float4*)in;
    #pragma unroll
    for (int i = tid; i < 4096; i += 256) {
        int row = i >> 5, q = i & 31;
        int node = nb + row < n ? nb + row : n - 1;
        float4 v = In4[(size_t)node * 32 + q];
        v.x = to_tf32(v.x); v.y = to_tf32(v.y);
        v.z = to_tf32(v.z); v.w = to_tf32(v.w);
        *(float4*)(Asm + row * ASTRIDE + q * 4) = v;
    }
    // stage W transposed (tf32-rounded): W[k][c] -> Wt[c][k]
    const float4* W4 = (const float4*)W;
    #pragma unroll
    for (int i = tid; i < 4096; i += 256) {
        int k = i >> 5, q = i & 31;
        float4 v = W4[k * 32 + q];
        Wt[(q * 4 + 0) * ASTRIDE + k] = to_tf32(v.x);
        Wt[(q * 4 + 1) * ASTRIDE + k] = to_tf32(v.y);
        Wt[(q * 4 + 2) * ASTRIDE + k] = to_tf32(v.z);
        Wt[(q * 4 + 3) * ASTRIDE + k] = to_tf32(v.w);
    }
    __syncthreads();

    int strip = (w >> 1) * 32;     // 0,32,64,96
    int chalf = (w & 1) * 64;      // 0 or 64
    int gid = lane >> 2, tg = lane & 3;

    float acc[2][8][4];
    #pragma unroll
    for (int r = 0; r < 2; r++)
        #pragma unroll
        for (int j = 0; j < 8; j++)
            #pragma unroll
            for (int q = 0; q < 4; q++) acc[r][j][q] = 0.f;

    const float* A0 = Asm + (strip + gid) * ASTRIDE + tg;       // r=0 row base
    const float* B0 = Wt + (chalf + gid) * ASTRIDE + tg;        // n-tile 0 base

    #pragma unroll 4
    for (int ks = 0; ks < 16; ks++) {
        int k0 = ks * 8;
        uint32_t a[2][4];
        #pragma unroll
        for (int r = 0; r < 2; r++) {
            const float* p = A0 + r * 16 * ASTRIDE + k0;
            a[r][0] = __float_as_uint(p[0]);
            a[r][1] = __float_as_uint(p[8 * ASTRIDE]);
            a[r][2] = __float_as_uint(p[4]);
            a[r][3] = __float_as_uint(p[8 * ASTRIDE + 4]);
        }
        #pragma unroll
        for (int j = 0; j < 8; j++) {
            const float* q = B0 + j * 8 * ASTRIDE + k0;
            uint32_t b0 = __float_as_uint(q[0]);
            uint32_t b1 = __float_as_uint(q[4]);
            mma_tf32(acc[0][j], a[0], b0, b1);
            mma_tf32(acc[1][j], a[1], b0, b1);
        }
    }

    // epilogue: bias + tanh + store (float2 per row-half)
    #pragma unroll
    for (int j = 0; j < 8; j++) {
        int col = chalf + 8 * j + 2 * tg;
        float2 bv = BIAS ? __ldg((const float2*)(bias + col)) : make_float2(0.f, 0.f);
        #pragma unroll
        for (int r = 0; r < 2; r++) {
            int row0 = nb + strip + r * 16 + gid;
            int row1 = row0 + 8;
            float v0 = acc[r][j][0] + bv.x;
            float v1 = acc[r][j][1] + bv.y;
            float v2 = acc[r][j][2] + bv.x;
            float v3 = acc[r][j][3] + bv.y;
            if (TANH) {
                v0 = fast_tanh(v0); v1 = fast_tanh(v1);
                v2 = fast_tanh(v2); v3 = fast_tanh(v3);
            }
            if (row0 < n) *(float2*)(out + (size_t)row0 * 128 + col) = make_float2(v0, v1);
            if (row1 < n) *(float2*)(out + (size_t)row1 * 128 + col) = make_float2(v2, v3);
        }
    }
}

// ---------------- final 128 -> 3 ----------------
__global__ void __launch_bounds__(256) out_k(
    const float* __restrict__ h, const float* __restrict__ lw4,
    const float* __restrict__ lb4, float* __restrict__ out, int n)
{
    int wid = (blockIdx.x * 256 + threadIdx.x) >> 5;
    int lane = threadIdx.x & 31;
    if (wid >= n) return;
    const float* row = h + (size_t)wid * 128;
    float a0 = 0.f, a1 = 0.f, a2 = 0.f;
    #pragma unroll
    for (int k = lane; k < 128; k += 32) {
        float hv = row[k];
        a0 = fmaf(hv, __ldg(&lw4[k * 3 + 0]), a0);
        a1 = fmaf(hv, __ldg(&lw4[k * 3 + 1]), a1);
        a2 = fmaf(hv, __ldg(&lw4[k * 3 + 2]), a2);
    }
    #pragma unroll
    for (int o = 16; o; o >>= 1) {
        a0 += __shfl_down_sync(0xffffffffu, a0, o);
        a1 += __shfl_down_sync(0xffffffffu, a1, o);
        a2 += __shfl_down_sync(0xffffffffu, a2, o);
    }
    if (lane == 0) {
        out[(size_t)wid * 3 + 0] = a0 + lb4[0];
        out[(size_t)wid * 3 + 1] = a1 + lb4[1];
        out[(size_t)wid * 3 + 2] = a2 + lb4[2];
    }
}

// ---------------- launch ----------------
extern "C" void kernel_launch(void* const* d_in, const int* in_sizes, int n_in,
                              void* d_out, int out_size)
{
    const float* x   = (const float*)d_in[0];
    const void*  ei  = d_in[1];
    const float* W1  = (const float*)d_in[2];
    const float* b1  = (const float*)d_in[3];
    const float* W2  = (const float*)d_in[4];
    const float* b2  = (const float*)d_in[5];
    const float* lw1 = (const float*)d_in[6];
    const float* lb1 = (const float*)d_in[7];
    const float* lw2 = (const float*)d_in[8];
    const float* lb2 = (const float*)d_in[9];
    const float* lw3 = (const float*)d_in[10];
    const float* lb3 = (const float*)d_in[11];
    const float* lw4 = (const float*)d_in[12];
    const float* lb4 = (const float*)d_in[13];
    float* out = (float*)d_out;

    int n = in_sizes[0] / H;
    long long E = (long long)in_sizes[1] / 2;

    float *pX, *pA, *pD, *pNrm;
    int *pDeg, *pOff, *pCur, *pSrc;
    cudaGetSymbolAddress((void**)&pX, g_X);
    cudaGetSymbolAddress((void**)&pA, g_A);
    cudaGetSymbolAddress((void**)&pD, g_dinv);
    cudaGetSymbolAddress((void**)&pDeg, g_deg);
    cudaGetSymbolAddress((void**)&pOff, g_off);
    cudaGetSymbolAddress((void**)&pCur, g_cur);
    cudaGetSymbolAddress((void**)&pSrc, g_csrc);
    cudaGetSymbolAddress((void**)&pNrm, g_cnrm);

    cudaFuncSetAttribute(gemm_tc<false, false>, cudaFuncAttributeMaxDynamicSharedMemorySize, TC_SMEM);
    cudaFuncSetAttribute(gemm_tc<true,  true>,  cudaFuncAttributeMaxDynamicSharedMemorySize, TC_SMEM);

    int gb  = (n + 127) / 128;             // gemm blocks
    int nwb = (n + 7) / 8;                 // warp-per-node blocks
    int eb  = (int)((E + 255) / 256);      // thread-per-edge blocks

    // Launch order keeps the GEMM at index 3 so ncu (-s 5 -c 1) profiles it.
    detect_k<<<1, 256>>>((const int*)ei);                                  // 0
    zeroi_k<<<(100352 / 4 + 255) / 256, 256>>>((int4*)pDeg, 100352 / 4);   // 1
    deg_k<<<eb, 256>>>(ei, E, pDeg);                                       // 2
    gemm_tc<false, false><<<gb, 256, TC_SMEM>>>(x, W1, nullptr, pX, n);    // 3 <- profiled
    dinv_k<<<(n + 255) / 256, 256>>>(pDeg, pD, n);                         // 4
    scan_k<<<1, 1024>>>(pDeg, pOff, pCur, n);                              // 5
    fill_k<<<eb, 256>>>(ei, E, pD, pCur, pSrc, pNrm);                      // 6

    // conv1 aggregate
    aggregate_k<<<nwb, 256>>>(pX, pOff, pDeg, pSrc, pNrm, pD, b1, pA, n);

    // conv2
    gemm_tc<false, false><<<gb, 256, TC_SMEM>>>(pA, W2, nullptr, pX, n);
    aggregate_k<<<nwb, 256>>>(pX, pOff, pDeg, pSrc, pNrm, pD, b2, pA, n);

    // MLP head
    gemm_tc<true, true><<<gb, 256, TC_SMEM>>>(pA, lw1, lb1, pX, n);
    gemm_tc<true, true><<<gb, 256, TC_SMEM>>>(pX, lw2, lb2, pA, n);
    gemm_tc<true, true><<<gb, 256, TC_SMEM>>>(pA, lw3, lb3, pX, n);
    out_k<<<(n + 7) / 8, 256>>>(pX, lw4, lb4, out, n);
}

// round 9
// speedup vs baseline: 2.2019x; 1.2544x over previous
#include <cuda_runtime.h>
#include <cstdint>

#define NN 100000
#define EE 3200000
#define H 128

// ---------------- scratch (__device__ globals; allocation-free rule) ----------------
__device__ float g_X[(size_t)NN * H];   // 51.2 MB ping
__device__ float g_A[(size_t)NN * H];   // 51.2 MB pong
__device__ float g_dinv[NN];
__device__ int   g_deg[100352];         // padded for int4 zeroing
__device__ int   g_off[NN + 1];
__device__ int   g_cur[100352];
__device__ int   g_csrc[EE];            // CSR: src per incoming edge of dst
__device__ float g_cnrm[EE];            // CSR: norm per incoming edge
__device__ int   g_is64;

__device__ __forceinline__ float fast_tanh(float x) {
    float t = __expf(-2.0f * fabsf(x));
    float r = __fdividef(1.0f - t, 1.0f + t);
    return copysignf(r, x);
}

// ---------------- edge dtype detection (int32 vs int64) ----------------
__global__ void detect_k(const int* __restrict__ ei32) {
    __shared__ int nz;
    if (threadIdx.x == 0) nz = 0;
    __syncthreads();
    int c = 0;
    for (int k = threadIdx.x; k < 4096; k += blockDim.x)
        if (ei32[2 * k + 1] != 0) c++;
    atomicAdd(&nz, c);
    __syncthreads();
    if (threadIdx.x == 0) g_is64 = (nz == 0) ? 1 : 0;
}

__device__ __forceinline__ int edge_val(const void* ei, long long E, long long idx, int row) {
    if (g_is64) return (int)((const long long*)ei)[row ? E + idx : idx];
    return ((const int*)ei)[row ? E + idx : idx];
}

// ---------------- zero ints ----------------
__global__ void zeroi_k(int4* __restrict__ p, int n4) {
    int i = blockIdx.x * blockDim.x + threadIdx.x;
    if (i < n4) p[i] = make_int4(0, 0, 0, 0);
}

// ---------------- degree count ----------------
__global__ void deg_k(const void* __restrict__ ei, long long E, int* __restrict__ deg) {
    long long e = (long long)blockIdx.x * blockDim.x + threadIdx.x;
    if (e < E) atomicAdd(&deg[edge_val(ei, E, e, 1)], 1);
}

__global__ void dinv_k(const int* __restrict__ deg, float* __restrict__ dinv, int n) {
    int i = blockIdx.x * blockDim.x + threadIdx.x;
    if (i < n) dinv[i] = rsqrtf((float)deg[i] + 2.0f);   // improved self-loop: +2
}

// ---------------- single-block scan: deg -> off, cur ----------------
__global__ void __launch_bounds__(1024) scan_k(const int* __restrict__ deg,
                                               int* __restrict__ off,
                                               int* __restrict__ cur, int n) {
    __shared__ int part[1024];
    int t = threadIdx.x;
    int chunk = (n + 1023) / 1024;
    int lo = t * chunk, hi = lo + chunk < n ? lo + chunk : n;
    int s = 0;
    for (int i = lo; i < hi; i++) s += deg[i];
    part[t] = s;
    __syncthreads();
    for (int o = 1; o < 1024; o <<= 1) {
        int v = (t >= o) ? part[t - o] : 0;
        __syncthreads();
        part[t] += v;
        __syncthreads();
    }
    int base = (t == 0) ? 0 : part[t - 1];
    for (int i = lo; i < hi; i++) {
        off[i] = base; cur[i] = base; base += deg[i];
    }
    if (t == 0) off[n] = part[1023];
}

// ---------------- CSR fill ----------------
__global__ void fill_k(const void* __restrict__ ei, long long E,
                       const float* __restrict__ dinv,
                       int* __restrict__ cur, int* __restrict__ csrc,
                       float* __restrict__ cnrm) {
    long long e = (long long)blockIdx.x * blockDim.x + threadIdx.x;
    if (e >= E) return;
    int s = edge_val(ei, E, e, 0);
    int d = edge_val(ei, E, e, 1);
    int pos = atomicAdd(&cur[d], 1);
    csrc[pos] = s;
    cnrm[pos] = dinv[s] * dinv[d];
}

// ---------------- gather + conv epilogue: out = tanh(sum + xw*2dinv^2 + b) ----------------
__global__ void __launch_bounds__(256) aggregate_k(
    const float* __restrict__ xw, const int* __restrict__ off,
    const int* __restrict__ deg, const int* __restrict__ csrc,
    const float* __restrict__ cnrm, const float* __restrict__ dinv,
    const float* __restrict__ bias, float* __restrict__ out, int n)
{
    int node = (blockIdx.x * 256 + threadIdx.x) >> 5;
    int lane = threadIdx.x & 31;
    if (node >= n) return;
    int j = off[node];
    int end = j + deg[node];
    const float4* X4 = (const float4*)xw;
    float4 acc = make_float4(0.f, 0.f, 0.f, 0.f);
    for (; j + 1 < end; j += 2) {
        int s0 = __ldg(&csrc[j]);     int s1 = __ldg(&csrc[j + 1]);
        float n0 = __ldg(&cnrm[j]);   float n1 = __ldg(&cnrm[j + 1]);
        float4 v0 = X4[(size_t)s0 * 32 + lane];
        float4 v1 = X4[(size_t)s1 * 32 + lane];
        acc.x = fmaf(v0.x, n0, acc.x); acc.y = fmaf(v0.y, n0, acc.y);
        acc.z = fmaf(v0.z, n0, acc.z); acc.w = fmaf(v0.w, n0, acc.w);
        acc.x = fmaf(v1.x, n1, acc.x); acc.y = fmaf(v1.y, n1, acc.y);
        acc.z = fmaf(v1.z, n1, acc.z); acc.w = fmaf(v1.w, n1, acc.w);
    }
    if (j < end) {
        int s0 = __ldg(&csrc[j]);
        float n0 = __ldg(&cnrm[j]);
        float4 v0 = X4[(size_t)s0 * 32 + lane];
        acc.x = fmaf(v0.x, n0, acc.x); acc.y = fmaf(v0.y, n0, acc.y);
        acc.z = fmaf(v0.z, n0, acc.z); acc.w = fmaf(v0.w, n0, acc.w);
    }
    float di = dinv[node];
    float sw = 2.0f * di * di;
    float4 xv = X4[(size_t)node * 32 + lane];
    float4 bv = ((const float4*)bias)[lane];
    acc.x = fast_tanh(fmaf(xv.x, sw, acc.x) + bv.x);
    acc.y = fast_tanh(fmaf(xv.y, sw, acc.y) + bv.y);
    acc.z = fast_tanh(fmaf(xv.z, sw, acc.z) + bv.z);
    acc.w = fast_tanh(fmaf(xv.w, sw, acc.w) + bv.w);
    ((float4*)out)[(size_t)node * 32 + lane] = acc;
}

// ---------------- GEMM via tf32 mma.sync (tensor cores), v2 ----------------
// 512 threads / 16 warps; CTA tile 128x128, warp tile 32x32.
// A staged [row][k] stride 132 (A-frag banks = lane id, conflict-free).
// W staged NATURAL [k][c] stride 136 (B-frag banks = (8*tg+gid)%32, all
// distinct, conflict-free) — no transpose pass at all.
#define ASTRIDE 132
#define WSTRIDE 136
#define TC_SMEM ((128 * ASTRIDE + 128 * WSTRIDE) * 4)   // 137216 B

__device__ __forceinline__ float to_tf32(float x) {
    uint32_t u;
    asm("cvt.rna.tf32.f32 %0, %1;" : "=r"(u) : "f"(x));
    return __uint_as_float(u);
}

__device__ __forceinline__ void mma_tf32(float* c, const uint32_t* a,
                                         uint32_t b0, uint32_t b1) {
    asm volatile(
        "mma.sync.aligned.m16n8k8.row.col.f32.tf32.tf32.f32 "
        "{%0,%1,%2,%3}, {%4,%5,%6,%7}, {%8,%9}, {%0,%1,%2,%3};"
        : "+f"(c[0]), "+f"(c[1]), "+f"(c[2]), "+f"(c[3])
        : "r"(a[0]), "r"(a[1]), "r"(a[2]), "r"(a[3]), "r"(b0), "r"(b1));
}

template <bool TANH, bool BIAS>
__global__ void __launch_bounds__(512) gemm_tc(
    const float* __restrict__ in, const float* __restrict__ W,
    const float* __restrict__ bias, float* __restrict__ out, int n)
{
    extern __shared__ float sm[];
    float* Asm = sm;                        // [row][k] stride ASTRIDE
    float* Wn  = sm + 128 * ASTRIDE;        // [k][c]  stride WSTRIDE

    int tid = threadIdx.x, lane = tid & 31, w = tid >> 5;
    int nb = blockIdx.x * 128;

    // stage A (tf32-rounded), float4 per thread-iter: conflict-free
    const float4* In4 = (const float4*)in;
    #pragma unroll
    for (int i = tid; i < 4096; i += 512) {
        int row = i >> 5, q = i & 31;
        int node = nb + row < n ? nb + row : n - 1;
        float4 v = In4[(size_t)node * 32 + q];
        v.x = to_tf32(v.x); v.y = to_tf32(v.y);
        v.z = to_tf32(v.z); v.w = to_tf32(v.w);
        *(float4*)(Asm + row * ASTRIDE + q * 4) = v;
    }
    // stage W natural [k][c] (tf32-rounded): conflict-free float4 stores
    const float4* W4 = (const float4*)W;
    #pragma unroll
    for (int i = tid; i < 4096; i += 512) {
        int k = i >> 5, q = i & 31;
        float4 v = W4[k * 32 + q];
        v.x = to_tf32(v.x); v.y = to_tf32(v.y);
        v.z = to_tf32(v.z); v.w = to_tf32(v.w);
        *(float4*)(Wn + k * WSTRIDE + q * 4) = v;
    }
    __syncthreads();

    int strip  = (w >> 2) * 32;    // row strip: 0,32,64,96
    int nquart = (w & 3) * 32;     // col strip: 0,32,64,96
    int gid = lane >> 2, tg = lane & 3;

    float acc[2][4][4];
    #pragma unroll
    for (int r = 0; r < 2; r++)
        #pragma unroll
        for (int j = 0; j < 4; j++)
            #pragma unroll
            for (int q = 0; q < 4; q++) acc[r][j][q] = 0.f;

    const float* A0 = Asm + (strip + gid) * ASTRIDE + tg;
    const float* B0 = Wn + tg * WSTRIDE + nquart + gid;

    #pragma unroll 4
    for (int ks = 0; ks < 16; ks++) {
        int k0 = ks * 8;
        uint32_t a[2][4];
        #pragma unroll
        for (int r = 0; r < 2; r++) {
            const float* p = A0 + r * 16 * ASTRIDE + k0;
            a[r][0] = __float_as_uint(p[0]);
            a[r][1] = __float_as_uint(p[8 * ASTRIDE]);
            a[r][2] = __float_as_uint(p[4]);
            a[r][3] = __float_as_uint(p[8 * ASTRIDE + 4]);
        }
        const float* q = B0 + k0 * WSTRIDE;
        #pragma unroll
        for (int j = 0; j < 4; j++) {
            uint32_t b0 = __float_as_uint(q[j * 8]);
            uint32_t b1 = __float_as_uint(q[4 * WSTRIDE + j * 8]);
            mma_tf32(acc[0][j], a[0], b0, b1);
            mma_tf32(acc[1][j], a[1], b0, b1);
        }
    }

    // epilogue: bias + tanh + float2 stores
    #pragma unroll
    for (int j = 0; j < 4; j++) {
        int col = nquart + 8 * j + 2 * tg;
        float2 bv = BIAS ? __ldg((const float2*)(bias + col)) : make_float2(0.f, 0.f);
        #pragma unroll
        for (int r = 0; r < 2; r++) {
            int row0 = nb + strip + r * 16 + gid;
            int row1 = row0 + 8;
            float v0 = acc[r][j][0] + bv.x;
            float v1 = acc[r][j][1] + bv.y;
            float v2 = acc[r][j][2] + bv.x;
            float v3 = acc[r][j][3] + bv.y;
            if (TANH) {
                v0 = fast_tanh(v0); v1 = fast_tanh(v1);
                v2 = fast_tanh(v2); v3 = fast_tanh(v3);
            }
            if (row0 < n) *(float2*)(out + (size_t)row0 * 128 + col) = make_float2(v0, v1);
            if (row1 < n) *(float2*)(out + (size_t)row1 * 128 + col) = make_float2(v2, v3);
        }
    }
}

// ---------------- final 128 -> 3 ----------------
__global__ void __launch_bounds__(256) out_k(
    const float* __restrict__ h, const float* __restrict__ lw4,
    const float* __restrict__ lb4, float* __restrict__ out, int n)
{
    int wid = (blockIdx.x * 256 + threadIdx.x) >> 5;
    int lane = threadIdx.x & 31;
    if (wid >= n) return;
    const float* row = h + (size_t)wid * 128;
    float a0 = 0.f, a1 = 0.f, a2 = 0.f;
    #pragma unroll
    for (int k = lane; k < 128; k += 32) {
        float hv = row[k];
        a0 = fmaf(hv, __ldg(&lw4[k * 3 + 0]), a0);
        a1 = fmaf(hv, __ldg(&lw4[k * 3 + 1]), a1);
        a2 = fmaf(hv, __ldg(&lw4[k * 3 + 2]), a2);
    }
    #pragma unroll
    for (int o = 16; o; o >>= 1) {
        a0 += __shfl_down_sync(0xffffffffu, a0, o);
        a1 += __shfl_down_sync(0xffffffffu, a1, o);
        a2 += __shfl_down_sync(0xffffffffu, a2, o);
    }
    if (lane == 0) {
        out[(size_t)wid * 3 + 0] = a0 + lb4[0];
        out[(size_t)wid * 3 + 1] = a1 + lb4[1];
        out[(size_t)wid * 3 + 2] = a2 + lb4[2];
    }
}

// ---------------- launch ----------------
extern "C" void kernel_launch(void* const* d_in, const int* in_sizes, int n_in,
                              void* d_out, int out_size)
{
    const float* x   = (const float*)d_in[0];
    const void*  ei  = d_in[1];
    const float* W1  = (const float*)d_in[2];
    const float* b1  = (const float*)d_in[3];
    const float* W2  = (const float*)d_in[4];
    const float* b2  = (const float*)d_in[5];
    const float* lw1 = (const float*)d_in[6];
    const float* lb1 = (const float*)d_in[7];
    const float* lw2 = (const float*)d_in[8];
    const float* lb2 = (const float*)d_in[9];
    const float* lw3 = (const float*)d_in[10];
    const float* lb3 = (const float*)d_in[11];
    const float* lw4 = (const float*)d_in[12];
    const float* lb4 = (const float*)d_in[13];
    float* out = (float*)d_out;

    int n = in_sizes[0] / H;
    long long E = (long long)in_sizes[1] / 2;

    float *pX, *pA, *pD, *pNrm;
    int *pDeg, *pOff, *pCur, *pSrc;
    cudaGetSymbolAddress((void**)&pX, g_X);
    cudaGetSymbolAddress((void**)&pA, g_A);
    cudaGetSymbolAddress((void**)&pD, g_dinv);
    cudaGetSymbolAddress((void**)&pDeg, g_deg);
    cudaGetSymbolAddress((void**)&pOff, g_off);
    cudaGetSymbolAddress((void**)&pCur, g_cur);
    cudaGetSymbolAddress((void**)&pSrc, g_csrc);
    cudaGetSymbolAddress((void**)&pNrm, g_cnrm);

    cudaFuncSetAttribute(gemm_tc<false, false>, cudaFuncAttributeMaxDynamicSharedMemorySize, TC_SMEM);
    cudaFuncSetAttribute(gemm_tc<true,  true>,  cudaFuncAttributeMaxDynamicSharedMemorySize, TC_SMEM);

    int gb  = (n + 127) / 128;             // gemm blocks
    int nwb = (n + 7) / 8;                 // warp-per-node blocks
    int eb  = (int)((E + 255) / 256);      // thread-per-edge blocks

    // Launch order keeps the GEMM at index 3 so ncu (-s 5 -c 1) profiles it.
    detect_k<<<1, 256>>>((const int*)ei);                                  // 0
    zeroi_k<<<(100352 / 4 + 255) / 256, 256>>>((int4*)pDeg, 100352 / 4);   // 1
    deg_k<<<eb, 256>>>(ei, E, pDeg);                                       // 2
    gemm_tc<false, false><<<gb, 512, TC_SMEM>>>(x, W1, nullptr, pX, n);    // 3 <- profiled
    dinv_k<<<(n + 255) / 256, 256>>>(pDeg, pD, n);                         // 4
    scan_k<<<1, 1024>>>(pDeg, pOff, pCur, n);                              // 5
    fill_k<<<eb, 256>>>(ei, E, pD, pCur, pSrc, pNrm);                      // 6

    // conv1 aggregate
    aggregate_k<<<nwb, 256>>>(pX, pOff, pDeg, pSrc, pNrm, pD, b1, pA, n);

    // conv2
    gemm_tc<false, false><<<gb, 512, TC_SMEM>>>(pA, W2, nullptr, pX, n);
    aggregate_k<<<nwb, 256>>>(pX, pOff, pDeg, pSrc, pNrm, pD, b2, pA, n);

    // MLP head
    gemm_tc<true, true><<<gb, 512, TC_SMEM>>>(pA, lw1, lb1, pX, n);
    gemm_tc<true, true><<<gb, 512, TC_SMEM>>>(pX, lw2, lb2, pA, n);
    gemm_tc<true, true><<<gb, 512, TC_SMEM>>>(pA, lw3, lb3, pX, n);
    out_k<<<(n + 7) / 8, 256>>>(pX, lw4, lb4, out, n);
}